// round 15
// baseline (speedup 1.0000x reference)
#include <cuda_runtime.h>
#include <math.h>

// Problem constants (match reference)
#define H_DIM   256
#define L_SEQ   512
#define N_BATCH 512
#define MAXC    64

// Precomputed positional embedding: 512 rows x 256 dims = 512 KB.
__device__ float g_pe[L_SEQ * H_DIM];

// ---------------------------------------------------------------------------
// Kernel 1: positional embedding, computed per launch (must be deterministic,
// no caching allowed). Double precision: angles reach ~511 rad; fast-math
// sinf argument reduction is unusable there. ~2 us.
// ---------------------------------------------------------------------------
__global__ void pe_kernel() {
    int row = blockIdx.x;          // 0..511
    int i   = threadIdx.x;         // 0..127  (pair index)
    double factor = exp(-((double)i) * (9.210340371976184 / 128.0)); // ln(10000)
    double ang = (double)row * factor;
    double s, c;
    sincos(ang, &s, &c);
    g_pe[row * H_DIM + 2 * i]     = (float)s;
    g_pe[row * H_DIM + 2 * i + 1] = (float)c;
}

// ---------------------------------------------------------------------------
// Kernel 2: main embedding, unroll-8 over n for memory-level parallelism.
// Grid: 512 rows x 16 n-chunks = 8192 blocks, 256 threads.
//   row    = bid >> 4
//   n_base = (bid & 15) * 32
//   thread t: h4 = t & 63 (float4 col), g = t >> 6 (0..3)
//   handles n = n_base + g + {0,4,...,28} -> 8 independent load chains.
// __launch_bounds__(256, 6): pin regs <= 42 so 6 blocks (48 warps) are
// resident per SM. Round-11 showed residency fell to ~4 blocks/SM (occ 52%),
// cancelling the MLP gain; this buys ~45% more outstanding chains per SM.
// Stores use __stcs (evict-first): output is never re-read.
// ---------------------------------------------------------------------------
__global__ __launch_bounds__(256, 6)
void embed_kernel(const float* __restrict__ u_in,            // (N, L, 3)
                  const float* __restrict__ w_num,           // (32, 256)
                  const float* __restrict__ cat_table,       // (n_emb, 256)
                  const int*   __restrict__ num_param_types, // (256,)
                  const int*   __restrict__ easy_index,      // (2048,)
                  float*       __restrict__ out)             // (N, L, H)
{
    const int bid    = blockIdx.x;
    const int row    = bid >> 4;           // 0..511
    const int n_base = (bid & 15) << 5;    // 0,32,...,480
    const int t      = threadIdx.x;
    const int g      = t >> 6;             // 0..3
    const int h4     = t & 63;             // float4 index within H

    const float4 pe = *reinterpret_cast<const float4*>(&g_pe[row * H_DIM + (h4 << 2)]);

    const int  n0    = n_base + g;                       // j-th n = n0 + 4*j
    const long urow0 = ((long)n0 * L_SEQ + row) * 3;     // +j*4*512*3
    float4* const out4 = reinterpret_cast<float4*>(out);
    const long obase = ((long)n0 * L_SEQ + row) * (H_DIM / 4) + h4;  // +j*4*512*64

    float4 r[8];

    if (row & 1) {
        // categorical rows: u -> easy_index -> cat_table gather, 8-wide MLP
        float tpar[8], cval[8];
#pragma unroll
        for (int j = 0; j < 8; j++) {
            const long u = urow0 + (long)j * (4L * L_SEQ * 3);
            tpar[j] = u_in[u + 2];
            cval[j] = u_in[u + 0];
        }
        int ei[8];
#pragma unroll
        for (int j = 0; j < 8; j++) {
            int big = __float2int_rn(tpar[j] * (float)MAXC + cval[j]);
            ei[j] = easy_index[big];
        }
#pragma unroll
        for (int j = 0; j < 8; j++) {
            const float4 e = *reinterpret_cast<const float4*>(
                &cat_table[(long)ei[j] * H_DIM + (h4 << 2)]);
            r[j].x = e.x + pe.x; r[j].y = e.y + pe.y;
            r[j].z = e.z + pe.z; r[j].w = e.w + pe.w;
        }
    } else {
        // numerical rows: w row depends only on `row` -> single w load
        float val[8];
#pragma unroll
        for (int j = 0; j < 8; j++) {
            const long u = urow0 + (long)j * (4L * L_SEQ * 3);
            val[j] = 2.0f * (u_in[u + 1] - 0.5f);
        }
        const int pt = num_param_types[row >> 1];
        const float4 w = *reinterpret_cast<const float4*>(
            &w_num[(long)pt * H_DIM + (h4 << 2)]);
#pragma unroll
        for (int j = 0; j < 8; j++) {
            r[j].x = fmaf(val[j], w.x, pe.x);
            r[j].y = fmaf(val[j], w.y, pe.y);
            r[j].z = fmaf(val[j], w.z, pe.z);
            r[j].w = fmaf(val[j], w.w, pe.w);
        }
    }

#pragma unroll
    for (int j = 0; j < 8; j++) {
        __stcs(&out4[obase + (long)j * (4L * L_SEQ * (H_DIM / 4))], r[j]);
    }
}

// ---------------------------------------------------------------------------
// Launch. Inputs (metadata order):
//   0: u_in (N,L,3) f32   1: w_num (8192,1) f32   2: cat_table f32
//   3: cat_rows i32       4: num_rows i32         5: num_param_types i32
//   6: easy_index i32
// ---------------------------------------------------------------------------
extern "C" void kernel_launch(void* const* d_in, const int* in_sizes, int n_in,
                              void* d_out, int out_size) {
    const float* u_in      = (const float*)d_in[0];
    const float* w_num     = (const float*)d_in[1];
    const float* cat_table = (const float*)d_in[2];
    const int*   npt       = (const int*)d_in[5];
    const int*   easy      = (const int*)d_in[6];
    float* out = (float*)d_out;

    pe_kernel<<<L_SEQ, H_DIM / 2>>>();
    embed_kernel<<<L_SEQ * (N_BATCH / 32), 256>>>(u_in, w_num, cat_table, npt, easy, out);
}

// round 16
// speedup vs baseline: 1.0870x; 1.0870x over previous
#include <cuda_runtime.h>
#include <math.h>

// Problem constants (match reference)
#define H_DIM   256
#define L_SEQ   512
#define N_BATCH 512
#define MAXC    64

// ---------------------------------------------------------------------------
// Single fused kernel.
// Grid: 512 rows x 4 n-quarters = 2048 blocks, 256 threads.
//   row = bid >> 2, q = bid & 3  -> n in [q*128, q*128+128)
//   thread t: g = t >> 6 (0..3), h4 = t & 63 (float4 column)
//   owns n = q*128 + g + 4*(c*8 + j), c in 0..3 (outer loop), j in 0..7
//   -> 8 independent load chains per iteration (the proven R11 mainloop).
// Positional embedding: first 128 threads compute the row's 128 double
// sincos pairs into smem (fuses away the separate pe kernel + graph gap;
// ~13M DP ops chip-wide ~ 2-3 us, overlapped with memory traffic).
// __launch_bounds__(256,4): R11's best-known codegen (42 regs, no shaving).
// Stores use __stcs (evict-first): output is never re-read.
// ---------------------------------------------------------------------------
__global__ __launch_bounds__(256, 4)
void embed_kernel(const float* __restrict__ u_in,            // (N, L, 3)
                  const float* __restrict__ w_num,           // (32, 256)
                  const float* __restrict__ cat_table,       // (n_emb, 256)
                  const int*   __restrict__ num_param_types, // (256,)
                  const int*   __restrict__ easy_index,      // (2048,)
                  float*       __restrict__ out)             // (N, L, H)
{
    __shared__ float s_pe[H_DIM];

    const int bid = blockIdx.x;
    const int row = bid >> 2;              // 0..511
    const int q   = bid & 3;               // n-quarter
    const int t   = threadIdx.x;

    // pe prologue: pe[2i]=sin(row*10000^(-i/128)), pe[2i+1]=cos(...).
    // Double precision: angles reach ~511 rad; fast-math sinf reduction is
    // unusable there. Identical formula to the reference.
    if (t < 128) {
        double factor = exp(-((double)t) * (9.210340371976184 / 128.0)); // ln(1e4)
        double s, c;
        sincos((double)row * factor, &s, &c);
        s_pe[2 * t]     = (float)s;
        s_pe[2 * t + 1] = (float)c;
    }
    __syncthreads();

    const int g  = t >> 6;                 // 0..3
    const int h4 = t & 63;                 // float4 index within H

    const float4 pe = *reinterpret_cast<const float4*>(&s_pe[h4 << 2]);

    const int n0 = (q << 7) + g;           // + 4*j + 32*c
    float4* const out4 = reinterpret_cast<float4*>(out);

    if (row & 1) {
        // categorical rows: u -> easy_index -> cat_table gather, 8-wide MLP
#pragma unroll
        for (int c = 0; c < 4; c++) {
            const int nc = n0 + (c << 5);
            const long urow0 = ((long)nc * L_SEQ + row) * 3;
            const long obase = ((long)nc * L_SEQ + row) * (H_DIM / 4) + h4;

            float tpar[8], cval[8];
#pragma unroll
            for (int j = 0; j < 8; j++) {
                const long u = urow0 + (long)j * (4L * L_SEQ * 3);
                tpar[j] = u_in[u + 2];
                cval[j] = u_in[u + 0];
            }
            int ei[8];
#pragma unroll
            for (int j = 0; j < 8; j++) {
                int big = __float2int_rn(tpar[j] * (float)MAXC + cval[j]);
                ei[j] = easy_index[big];
            }
            float4 r[8];
#pragma unroll
            for (int j = 0; j < 8; j++) {
                const float4 e = *reinterpret_cast<const float4*>(
                    &cat_table[(long)ei[j] * H_DIM + (h4 << 2)]);
                r[j].x = e.x + pe.x; r[j].y = e.y + pe.y;
                r[j].z = e.z + pe.z; r[j].w = e.w + pe.w;
            }
#pragma unroll
            for (int j = 0; j < 8; j++)
                __stcs(&out4[obase + (long)j * (4L * L_SEQ * (H_DIM / 4))], r[j]);
        }
    } else {
        // numerical rows: w row depends only on `row` -> single w load
        const int pt = num_param_types[row >> 1];
        const float4 w = *reinterpret_cast<const float4*>(
            &w_num[(long)pt * H_DIM + (h4 << 2)]);
#pragma unroll
        for (int c = 0; c < 4; c++) {
            const int nc = n0 + (c << 5);
            const long urow0 = ((long)nc * L_SEQ + row) * 3;
            const long obase = ((long)nc * L_SEQ + row) * (H_DIM / 4) + h4;

            float val[8];
#pragma unroll
            for (int j = 0; j < 8; j++) {
                const long u = urow0 + (long)j * (4L * L_SEQ * 3);
                val[j] = 2.0f * (u_in[u + 1] - 0.5f);
            }
            float4 r[8];
#pragma unroll
            for (int j = 0; j < 8; j++) {
                r[j].x = fmaf(val[j], w.x, pe.x);
                r[j].y = fmaf(val[j], w.y, pe.y);
                r[j].z = fmaf(val[j], w.z, pe.z);
                r[j].w = fmaf(val[j], w.w, pe.w);
            }
#pragma unroll
            for (int j = 0; j < 8; j++)
                __stcs(&out4[obase + (long)j * (4L * L_SEQ * (H_DIM / 4))], r[j]);
        }
    }
}

// ---------------------------------------------------------------------------
// Launch. Inputs (metadata order):
//   0: u_in (N,L,3) f32   1: w_num (8192,1) f32   2: cat_table f32
//   3: cat_rows i32       4: num_rows i32         5: num_param_types i32
//   6: easy_index i32
// ---------------------------------------------------------------------------
extern "C" void kernel_launch(void* const* d_in, const int* in_sizes, int n_in,
                              void* d_out, int out_size) {
    const float* u_in      = (const float*)d_in[0];
    const float* w_num     = (const float*)d_in[1];
    const float* cat_table = (const float*)d_in[2];
    const int*   npt       = (const int*)d_in[5];
    const int*   easy      = (const int*)d_in[6];
    float* out = (float*)d_out;

    embed_kernel<<<L_SEQ * 4, 256>>>(u_in, w_num, cat_table, npt, easy, out);
}

// round 17
// speedup vs baseline: 1.0962x; 1.0084x over previous
#include <cuda_runtime.h>
#include <math.h>

// Problem constants (match reference)
#define H_DIM   256
#define L_SEQ   512
#define N_BATCH 512
#define MAXC    64

// Precomputed positional embedding: 512 rows x 256 dims = 512 KB.
__device__ float g_pe[L_SEQ * H_DIM];

// ---------------------------------------------------------------------------
// Kernel 1: positional embedding (identical numerics to the proven R11/R3
// version; rel_err 2.66e-6). Double precision because angles reach ~511 rad.
// Signals programmatic completion after its stores so the PDL-launched
// embed_kernel can overlap its own launch/startup with this kernel.
// ---------------------------------------------------------------------------
__global__ void pe_kernel() {
    int row = blockIdx.x;          // 0..511
    int i   = threadIdx.x;         // 0..127  (pair index)
    double factor = exp(-((double)i) * (9.210340371976184 / 128.0)); // ln(10000)
    double ang = (double)row * factor;
    double s, c;
    sincos(ang, &s, &c);
    g_pe[row * H_DIM + 2 * i]     = (float)s;
    g_pe[row * H_DIM + 2 * i + 1] = (float)c;
    cudaTriggerProgrammaticLaunchCompletion();
}

// ---------------------------------------------------------------------------
// Kernel 2: main embedding — the R11 body verbatim (best measured: 43.8 us,
// 42 regs, grid 8192) plus a grid-dependency sync at the top. Launched with
// the PDL attribute so it starts while pe_kernel drains; the sync guarantees
// g_pe is visible before any thread proceeds.
// Grid: 512 rows x 16 n-chunks = 8192 blocks, 256 threads.
//   row = bid >> 4, n_base = (bid & 15)*32
//   thread t: h4 = t & 63, g = t >> 6; n = n_base + g + {0,4,...,28}
//   -> 8 independent load chains per thread.
// Stores use __stcs (evict-first): output is never re-read.
// ---------------------------------------------------------------------------
__global__ __launch_bounds__(256, 4)
void embed_kernel(const float* __restrict__ u_in,            // (N, L, 3)
                  const float* __restrict__ w_num,           // (32, 256)
                  const float* __restrict__ cat_table,       // (n_emb, 256)
                  const int*   __restrict__ num_param_types, // (256,)
                  const int*   __restrict__ easy_index,      // (2048,)
                  float*       __restrict__ out)             // (N, L, H)
{
    cudaGridDependencySynchronize();   // g_pe ready (PDL edge to pe_kernel)

    const int bid    = blockIdx.x;
    const int row    = bid >> 4;           // 0..511
    const int n_base = (bid & 15) << 5;    // 0,32,...,480
    const int t      = threadIdx.x;
    const int g      = t >> 6;             // 0..3
    const int h4     = t & 63;             // float4 index within H

    const float4 pe = *reinterpret_cast<const float4*>(&g_pe[row * H_DIM + (h4 << 2)]);

    const int  n0    = n_base + g;                       // j-th n = n0 + 4*j
    const long urow0 = ((long)n0 * L_SEQ + row) * 3;     // +j*4*512*3
    float4* const out4 = reinterpret_cast<float4*>(out);
    const long obase = ((long)n0 * L_SEQ + row) * (H_DIM / 4) + h4;  // +j*4*512*64

    float4 r[8];

    if (row & 1) {
        // categorical rows: u -> easy_index -> cat_table gather, 8-wide MLP
        float tpar[8], cval[8];
#pragma unroll
        for (int j = 0; j < 8; j++) {
            const long u = urow0 + (long)j * (4L * L_SEQ * 3);
            tpar[j] = u_in[u + 2];
            cval[j] = u_in[u + 0];
        }
        int ei[8];
#pragma unroll
        for (int j = 0; j < 8; j++) {
            int big = __float2int_rn(tpar[j] * (float)MAXC + cval[j]);
            ei[j] = easy_index[big];
        }
#pragma unroll
        for (int j = 0; j < 8; j++) {
            const float4 e = *reinterpret_cast<const float4*>(
                &cat_table[(long)ei[j] * H_DIM + (h4 << 2)]);
            r[j].x = e.x + pe.x; r[j].y = e.y + pe.y;
            r[j].z = e.z + pe.z; r[j].w = e.w + pe.w;
        }
    } else {
        // numerical rows: w row depends only on `row` -> single w load
        float val[8];
#pragma unroll
        for (int j = 0; j < 8; j++) {
            const long u = urow0 + (long)j * (4L * L_SEQ * 3);
            val[j] = 2.0f * (u_in[u + 1] - 0.5f);
        }
        const int pt = num_param_types[row >> 1];
        const float4 w = *reinterpret_cast<const float4*>(
            &w_num[(long)pt * H_DIM + (h4 << 2)]);
#pragma unroll
        for (int j = 0; j < 8; j++) {
            r[j].x = fmaf(val[j], w.x, pe.x);
            r[j].y = fmaf(val[j], w.y, pe.y);
            r[j].z = fmaf(val[j], w.z, pe.z);
            r[j].w = fmaf(val[j], w.w, pe.w);
        }
    }

#pragma unroll
    for (int j = 0; j < 8; j++) {
        __stcs(&out4[obase + (long)j * (4L * L_SEQ * (H_DIM / 4))], r[j]);
    }
}

// ---------------------------------------------------------------------------
// Launch. pe_kernel normally, then embed_kernel with the PDL attribute so it
// overlaps pe_kernel's tail + its own launch latency. Both on the default
// stream (graph capture records the PDL edge).
// Inputs (metadata order):
//   0: u_in (N,L,3) f32   1: w_num (8192,1) f32   2: cat_table f32
//   3: cat_rows i32       4: num_rows i32         5: num_param_types i32
//   6: easy_index i32
// ---------------------------------------------------------------------------
extern "C" void kernel_launch(void* const* d_in, const int* in_sizes, int n_in,
                              void* d_out, int out_size) {
    const float* u_in      = (const float*)d_in[0];
    const float* w_num     = (const float*)d_in[1];
    const float* cat_table = (const float*)d_in[2];
    const int*   npt       = (const int*)d_in[5];
    const int*   easy      = (const int*)d_in[6];
    float* out = (float*)d_out;

    pe_kernel<<<L_SEQ, H_DIM / 2>>>();

    cudaLaunchConfig_t cfg = {};
    cfg.gridDim  = dim3(L_SEQ * (N_BATCH / 32));
    cfg.blockDim = dim3(256);
    cfg.dynamicSmemBytes = 0;
    cfg.stream = 0;  // legacy default stream, same as <<<>>> above
    cudaLaunchAttribute attrs[1];
    attrs[0].id = cudaLaunchAttributeProgrammaticStreamSerialization;
    attrs[0].val.programmaticStreamSerializationAllowed = 1;
    cfg.attrs = attrs;
    cfg.numAttrs = 1;

    cudaLaunchKernelEx(&cfg, embed_kernel, u_in, w_num, cat_table, npt, easy, out);
}